// round 3
// baseline (speedup 1.0000x reference)
#include <cuda_runtime.h>
#include <math.h>

// ---------------------------------------------------------------------------
// Problem constants
// ---------------------------------------------------------------------------
#define S_LEN 1024
#define BATCH 2
#define NTOK  2048          // B*S
#define EDIM  512
#define HDIM  1024
#define MDIM  256
#define VDIM  32000

// ---------------------------------------------------------------------------
// Scratch (device globals: the sanctioned alternative to cudaMalloc)
// ---------------------------------------------------------------------------
__device__ float g_emb[NTOK * EDIM];                 // 4 MB
__device__ float g_xp[NTOK * 3 * HDIM];              // 25 MB
__device__ float g_states[NTOK * HDIM];              // 8 MB
__device__ float g_h[2 * BATCH * HDIM];              // ping-pong recurrent state
__device__ float g_hf[NTOK * 4 * EDIM];              // 16 MB
__device__ float g_base[NTOK * EDIM];                // 4 MB
__device__ float g_comb[NTOK * EDIM];                // 4 MB
__device__ float g_gate[NTOK];
__device__ float g_q[NTOK * MDIM];
__device__ float g_k[NTOK * MDIM];
__device__ unsigned g_bar_cnt;
__device__ unsigned g_bar_gen;

// ---------------------------------------------------------------------------
// Init: zero recurrent state + reset grid barrier
// ---------------------------------------------------------------------------
__global__ void init_kernel() {
    int i = blockIdx.x * blockDim.x + threadIdx.x;
    if (i < 2 * BATCH * HDIM) g_h[i] = 0.f;
    if (i == 0) { g_bar_cnt = 0u; g_bar_gen = 0u; }
}

// ---------------------------------------------------------------------------
// Embedding gather: emb[t] = emb_W[ids[t]]   (2048 x 512)
// ---------------------------------------------------------------------------
__global__ void embed_kernel(const int* __restrict__ ids,
                             const float* __restrict__ embW) {
    int t = blockIdx.x;
    int c = threadIdx.x;                       // 128 threads, one float4 each
    int id = ids[t];
    ((float4*)g_emb)[(size_t)t * (EDIM / 4) + c] =
        ((const float4*)embW)[(size_t)id * (EDIM / 4) + c];
}

// ---------------------------------------------------------------------------
// Generic SGEMM: C[m][n] = sum_k A[m][k]*B[n][k] (+ epilogue)
// A: [M,K] row-major, B: [N,K] row-major. M,N % 128 == 0, K % 16 == 0.
// epi 0: +bias[n]
// epi 1: relu(x+bias)^2
// epi 2: auxb[m][n] + auxg[m]*relu(x+bias)      (combined residual path)
// ---------------------------------------------------------------------------
__global__ void __launch_bounds__(256) sgemm_kernel(
    const float* __restrict__ A, const float* __restrict__ B,
    const float* __restrict__ bias, float* __restrict__ C,
    int M, int N, int K, int epi,
    const float* __restrict__ auxb, const float* __restrict__ auxg)
{
    __shared__ float As[16][132];
    __shared__ float Bs[16][132];
    const int tid = threadIdx.x;
    const int tx = tid & 15, ty = tid >> 4;
    const int row0 = blockIdx.y * 128, col0 = blockIdx.x * 128;

    float acc[8][8];
#pragma unroll
    for (int i = 0; i < 8; ++i)
#pragma unroll
        for (int j = 0; j < 8; ++j) acc[i][j] = 0.f;

    for (int k0 = 0; k0 < K; k0 += 16) {
#pragma unroll
        for (int i = 0; i < 2; ++i) {
            int v = tid + i * 256;
            int r = v >> 2;
            int kq = (v & 3) << 2;
            float4 av = *(const float4*)(A + (size_t)(row0 + r) * K + k0 + kq);
            As[kq + 0][r] = av.x; As[kq + 1][r] = av.y;
            As[kq + 2][r] = av.z; As[kq + 3][r] = av.w;
            float4 bv = *(const float4*)(B + (size_t)(col0 + r) * K + k0 + kq);
            Bs[kq + 0][r] = bv.x; Bs[kq + 1][r] = bv.y;
            Bs[kq + 2][r] = bv.z; Bs[kq + 3][r] = bv.w;
        }
        __syncthreads();
#pragma unroll
        for (int k = 0; k < 16; ++k) {
            float4 a0 = *(const float4*)&As[k][ty * 8];
            float4 a1 = *(const float4*)&As[k][ty * 8 + 4];
            float4 b0 = *(const float4*)&Bs[k][tx * 8];
            float4 b1 = *(const float4*)&Bs[k][tx * 8 + 4];
            float a[8] = {a0.x, a0.y, a0.z, a0.w, a1.x, a1.y, a1.z, a1.w};
            float b[8] = {b0.x, b0.y, b0.z, b0.w, b1.x, b1.y, b1.z, b1.w};
#pragma unroll
            for (int i = 0; i < 8; ++i)
#pragma unroll
                for (int j = 0; j < 8; ++j)
                    acc[i][j] = fmaf(a[i], b[j], acc[i][j]);
        }
        __syncthreads();
    }

#pragma unroll
    for (int i = 0; i < 8; ++i) {
        int m = row0 + ty * 8 + i;
#pragma unroll
        for (int j = 0; j < 8; j += 4) {
            int n = col0 + tx * 8 + j;
            float o[4];
#pragma unroll
            for (int u = 0; u < 4; ++u) {
                float x = acc[i][j + u] + bias[n + u];
                if (epi == 1) { x = fmaxf(x, 0.f); x = x * x; }
                else if (epi == 2) {
                    x = auxb[(size_t)m * N + n + u] + auxg[m] * fmaxf(x, 0.f);
                }
                o[u] = x;
            }
            float4 ov = make_float4(o[0], o[1], o[2], o[3]);
            *(float4*)(C + (size_t)m * N + n) = ov;
        }
    }
}

// ---------------------------------------------------------------------------
// GRU: persistent kernel. 128 CTAs x 256 threads, CTA c owns H-indices
// [8c, 8c+8). w_hh rows for its 24 (gate,index) rows live in SMEM for all
// 1024 steps. Grid barrier = monotonic counter + generation (no reset races).
// h ping-pongs through L2 via __ldcg/__stcg (L1 would go stale).
// ---------------------------------------------------------------------------
#define GRU_CTAS    128
#define GRU_THREADS 256
#define GRU_SMEM    ((24 * HDIM + BATCH * HDIM) * 4)

__device__ __forceinline__ float warp_sum(float v) {
#pragma unroll
    for (int o = 16; o; o >>= 1) v += __shfl_xor_sync(0xffffffffu, v, o);
    return v;
}

__global__ void __launch_bounds__(GRU_THREADS, 1) gru_kernel(
    const float* __restrict__ xp, const float* __restrict__ w_hh,
    const float* __restrict__ b_hh)
{
    extern __shared__ float sm[];
    float* wsm = sm;                       // [24][HDIM], row = gate*8 + jl
    float* hsm = sm + 24 * HDIM;           // [BATCH][HDIM]
    const int tid = threadIdx.x;
    const int w = tid >> 5, lane = tid & 31;
    const int j0 = blockIdx.x * 8;

    // Stage the 24 weight rows (96 KB) once.
    for (int v = tid; v < 24 * (HDIM / 4); v += GRU_THREADS) {
        int rowl = v / (HDIM / 4);
        int c4 = v % (HDIM / 4);
        int g = rowl >> 3, jl = rowl & 7;
        ((float4*)wsm)[(size_t)rowl * (HDIM / 4) + c4] =
            ((const float4*)w_hh)[(size_t)(g * HDIM + j0 + jl) * (HDIM / 4) + c4];
    }
    const int j = j0 + w;                  // this warp's H-index
    const float bhr = b_hh[j];
    const float bhz = b_hh[HDIM + j];
    const float bhn = b_hh[2 * HDIM + j];
    __syncthreads();

    for (int s = 0; s < S_LEN; ++s) {
        const float* h_in = g_h + (s & 1) * (BATCH * HDIM);
        float* h_out      = g_h + ((s + 1) & 1) * (BATCH * HDIM);

        // Pull h (2x1024) into SMEM through L2.
        for (int v = tid; v < (BATCH * HDIM) / 4; v += GRU_THREADS)
            ((float4*)hsm)[v] = __ldcg(((const float4*)h_in) + v);
        __syncthreads();

        // Lane l owns float4 chunks at offsets 4l + 128c (conflict-free).
        float4 H0[8], H1[8];
#pragma unroll
        for (int c = 0; c < 8; ++c) {
            H0[c] = ((const float4*)hsm)[lane + 32 * c];
            H1[c] = ((const float4*)(hsm + HDIM))[lane + 32 * c];
        }
        float acc[3][2];
#pragma unroll
        for (int g = 0; g < 3; ++g) {
            const float4* wp = (const float4*)(wsm + (size_t)(g * 8 + w) * HDIM);
            float s0a = 0.f, s0b = 0.f, s1a = 0.f, s1b = 0.f;
#pragma unroll
            for (int c = 0; c < 8; ++c) {
                float4 wv = wp[lane + 32 * c];
                s0a = fmaf(wv.x, H0[c].x, s0a); s0b = fmaf(wv.y, H0[c].y, s0b);
                s0a = fmaf(wv.z, H0[c].z, s0a); s0b = fmaf(wv.w, H0[c].w, s0b);
                s1a = fmaf(wv.x, H1[c].x, s1a); s1b = fmaf(wv.y, H1[c].y, s1b);
                s1a = fmaf(wv.z, H1[c].z, s1a); s1b = fmaf(wv.w, H1[c].w, s1b);
            }
            acc[g][0] = warp_sum(s0a + s0b);
            acc[g][1] = warp_sum(s1a + s1b);
        }
        if (lane == 0) {
#pragma unroll
            for (int b = 0; b < 2; ++b) {
                size_t t = (size_t)b * S_LEN + s;
                const float* xpt = xp + t * (3 * HDIM);
                float r = 1.f / (1.f + expf(-(xpt[j] + acc[0][b] + bhr)));
                float z = 1.f / (1.f + expf(-(xpt[HDIM + j] + acc[1][b] + bhz)));
                float n = tanhf(xpt[2 * HDIM + j] + r * (acc[2][b] + bhn));
                float hp = hsm[b * HDIM + j];
                float hn2 = (1.f - z) * n + z * hp;
                g_states[t * HDIM + j] = hn2;
                __stcg(h_out + b * HDIM + j, hn2);
            }
        }
        __syncthreads();
        // --- grid barrier (monotonic counter; gen = step+1) ---
        if (tid == 0) {
            __threadfence();
            unsigned prev = atomicAdd(&g_bar_cnt, 1u);
            unsigned tgt = (unsigned)(s + 1);
            if (prev == (unsigned)(GRU_CTAS * (s + 1) - 1)) {
                atomicExch(&g_bar_gen, tgt);
            } else {
                while (*((volatile unsigned*)&g_bar_gen) < tgt) __nanosleep(64);
            }
            __threadfence();
        }
        __syncthreads();
    }
}

// ---------------------------------------------------------------------------
// gate[t] = sigmoid(states[t] . Wg + bg)
// ---------------------------------------------------------------------------
__global__ void gate_kernel(const float* __restrict__ Wg,
                            const float* __restrict__ bg) {
    int t = blockIdx.x;
    int tid = threadIdx.x;                 // 128 threads
    const float4* sp = (const float4*)(g_states + (size_t)t * HDIM);
    const float4* wp = (const float4*)Wg;
    float s = 0.f;
    for (int c = tid; c < HDIM / 4; c += 128) {
        float4 a = sp[c], ww = wp[c];
        s += a.x * ww.x + a.y * ww.y + a.z * ww.z + a.w * ww.w;
    }
    __shared__ float red[128];
    red[tid] = s; __syncthreads();
    for (int k = 64; k; k >>= 1) {
        if (tid < k) red[tid] += red[tid + k];
        __syncthreads();
    }
    if (tid == 0) g_gate[t] = 1.f / (1.f + expf(-(red[0] + bg[0])));
}

// ---------------------------------------------------------------------------
// Fused attention softmax + scatter-add into logits.
// Strictly-causal (k < q); row q==0 contributes nothing. Masked terms are
// exactly zero in the reference (exp(finfo.min - max) == 0, renorm sum == 1),
// so attn == softmax over the valid prefix.
// ---------------------------------------------------------------------------
__global__ void __launch_bounds__(256) attn_scatter_kernel(
    const int* __restrict__ ids, const float* __restrict__ mscale,
    float* __restrict__ out)
{
    int bq = blockIdx.x;
    int b = bq >> 10, qpos = bq & 1023;
    if (qpos == 0) return;
    int tid = threadIdx.x;

    __shared__ float qv[MDIM];
    __shared__ float red[256];
    if (tid < MDIM) qv[tid] = g_q[(size_t)bq * MDIM + tid];
    __syncthreads();

    const int nk = qpos;
    float sc[4];
    int cnt = 0;
    float mx = -1e30f;
    for (int kp = tid; kp < nk; kp += 256) {
        const float4* kr = (const float4*)(g_k + (size_t)(b * S_LEN + kp) * MDIM);
        float d = 0.f;
#pragma unroll 16
        for (int c = 0; c < MDIM / 4; ++c) {
            float4 kv = kr[c];
            float4 qq = ((const float4*)qv)[c];
            d += kv.x * qq.x + kv.y * qq.y + kv.z * qq.z + kv.w * qq.w;
        }
        d *= 0.0625f;                      // 1/sqrt(256)
        sc[cnt++] = d;
        mx = fmaxf(mx, d);
    }
    red[tid] = mx; __syncthreads();
    for (int k = 128; k; k >>= 1) {
        if (tid < k) red[tid] = fmaxf(red[tid], red[tid + k]);
        __syncthreads();
    }
    mx = red[0]; __syncthreads();

    float sum = 0.f;
    for (int i = 0; i < cnt; ++i) { sc[i] = expf(sc[i] - mx); sum += sc[i]; }
    red[tid] = sum; __syncthreads();
    for (int k = 128; k; k >>= 1) {
        if (tid < k) red[tid] += red[tid + k];
        __syncthreads();
    }
    sum = red[0];

    float coef = g_gate[bq] * mscale[0] / sum;
    int i2 = 0;
    for (int kp = tid; kp < nk; kp += 256) {
        int vid = ids[b * S_LEN + kp];
        atomicAdd(out + (size_t)bq * VDIM + vid, sc[i2++] * coef);
    }
}

// ---------------------------------------------------------------------------
// Host launcher
// ---------------------------------------------------------------------------
extern "C" void kernel_launch(void* const* d_in, const int* in_sizes, int n_in,
                              void* d_out, int out_size) {
    (void)in_sizes; (void)n_in; (void)out_size;
    const int*   ids    = (const int*)d_in[0];
    const float* embW   = (const float*)d_in[1];
    const float* w_ih   = (const float*)d_in[2];
    const float* w_hh   = (const float*)d_in[3];
    const float* b_ih   = (const float*)d_in[4];
    const float* b_hh   = (const float*)d_in[5];
    const float* Wq     = (const float*)d_in[6];
    const float* bq     = (const float*)d_in[7];
    const float* Wk     = (const float*)d_in[8];
    const float* bk     = (const float*)d_in[9];
    const float* Wg     = (const float*)d_in[10];
    const float* bg     = (const float*)d_in[11];
    const float* W1     = (const float*)d_in[12];
    const float* b1     = (const float*)d_in[13];
    const float* W2     = (const float*)d_in[14];
    const float* b2     = (const float*)d_in[15];
    const float* Wr     = (const float*)d_in[16];
    const float* br     = (const float*)d_in[17];
    const float* mscale = (const float*)d_in[18];
    const float* obias  = (const float*)d_in[19];
    float* out = (float*)d_out;

    float *p_emb, *p_xp, *p_states, *p_hf, *p_base, *p_comb, *p_gate, *p_q, *p_k;
    cudaGetSymbolAddress((void**)&p_emb,    g_emb);
    cudaGetSymbolAddress((void**)&p_xp,     g_xp);
    cudaGetSymbolAddress((void**)&p_states, g_states);
    cudaGetSymbolAddress((void**)&p_hf,     g_hf);
    cudaGetSymbolAddress((void**)&p_base,   g_base);
    cudaGetSymbolAddress((void**)&p_comb,   g_comb);
    cudaGetSymbolAddress((void**)&p_gate,   g_gate);
    cudaGetSymbolAddress((void**)&p_q,      g_q);
    cudaGetSymbolAddress((void**)&p_k,      g_k);

    cudaFuncSetAttribute(gru_kernel,
                         cudaFuncAttributeMaxDynamicSharedMemorySize, GRU_SMEM);

    init_kernel<<<16, 256>>>();
    embed_kernel<<<NTOK, 128>>>(ids, embW);

    // xp = emb @ w_ih^T + b_ih    [2048, 3072]
    sgemm_kernel<<<dim3(3 * HDIM / 128, NTOK / 128), 256>>>(
        p_emb, w_ih, b_ih, p_xp, NTOK, 3 * HDIM, EDIM, 0, nullptr, nullptr);

    // Recurrent scan -> g_states
    gru_kernel<<<GRU_CTAS, GRU_THREADS, GRU_SMEM>>>(p_xp, w_hh, b_hh);

    // gate = sigmoid(states @ Wg^T + bg)
    gate_kernel<<<NTOK, 128>>>(Wg, bg);

    // hf = relu(states @ W1^T + b1)^2   [2048, 2048]
    sgemm_kernel<<<dim3(4 * EDIM / 128, NTOK / 128), 256>>>(
        p_states, W1, b1, p_hf, NTOK, 4 * EDIM, HDIM, 1, nullptr, nullptr);

    // base = hf @ W2^T + b2             [2048, 512]
    sgemm_kernel<<<dim3(EDIM / 128, NTOK / 128), 256>>>(
        p_hf, W2, b2, p_base, NTOK, EDIM, 4 * EDIM, 0, nullptr, nullptr);

    // comb = base + gate * relu(base @ Wr^T + br)   [2048, 512]
    sgemm_kernel<<<dim3(EDIM / 128, NTOK / 128), 256>>>(
        p_base, Wr, br, p_comb, NTOK, EDIM, EDIM, 2, p_base, p_gate);

    // q / k projections                 [2048, 256]
    sgemm_kernel<<<dim3(MDIM / 128, NTOK / 128), 256>>>(
        p_states, Wq, bq, p_q, NTOK, MDIM, HDIM, 0, nullptr, nullptr);
    sgemm_kernel<<<dim3(MDIM / 128, NTOK / 128), 256>>>(
        p_states, Wk, bk, p_k, NTOK, MDIM, HDIM, 0, nullptr, nullptr);

    // logits = comb @ emb_W^T + output_bias   [2048, 32000] -> d_out
    sgemm_kernel<<<dim3(VDIM / 128, NTOK / 128), 256>>>(
        p_comb, embW, obias, out, NTOK, VDIM, EDIM, 0, nullptr, nullptr);

    // softmax + scatter-add of gated attention into logits
    attn_scatter_kernel<<<NTOK, 256>>>(ids, mscale, out);
}